// round 3
// baseline (speedup 1.0000x reference)
#include <cuda_runtime.h>
#include <cuda_bf16.h>
#include <cstdint>

// LuGreCell: B=4096, T=2048, S=1, H=64.
// Kernel 1: precompute per (b,t): v, k=g*sign(v), c2=dt*ln2*|v|/g, Fs;
//           transpose to time-major [T][B] float4.
// Kernel 2: sequential scan, 1024 warps (4 batches/warp, 8 lanes/batch).
//   KEY: one-step predictor. The MLP (tanh block + shfl reduce + ex2/lg2)
//   for step t+1 is computed during step t from predictor sz_t; the on-path
//   correction is a single fma with the precomputed derivative q*sigma.
//   Critical chain per step: ~8 short FMA-class ops instead of tanh+shfl+exp.

#define BB 4096
#define TT 2048
#define HH 64

__device__ float4 g_pre[(size_t)BB * TT];  // 134 MB static scratch

__device__ __forceinline__ float ex2f_(float x){ float y; asm("ex2.approx.f32 %0, %1;":"=f"(y):"f"(x)); return y; }
__device__ __forceinline__ float lg2f_(float x){ float y; asm("lg2.approx.f32 %0, %1;":"=f"(y):"f"(x)); return y; }
__device__ __forceinline__ float tanhf_(float x){ float y; asm("tanh.approx.f32 %0, %1;":"=f"(y):"f"(x)); return y; }

#define LOG2E 1.4426950408889634f
#define C2COEF 6.931471805599453e-4f        /* dt*ln2 */
#define INVC   1442.6950408889634f          /* 1/(dt*ln2) */

// ---------------- Kernel 1: precompute + transpose ----------------
__global__ void __launch_bounds__(256) lugre_pre(
    const float* __restrict__ x,        // [B, T, 3]: v, F_c, F_s
    const float* __restrict__ alpha,
    const float* __restrict__ vs)
{
    __shared__ float4 tile[32][33];
    const int t0 = blockIdx.x * 32;
    const int b0 = blockIdx.y * 32;
    const float a0  = alpha[0];
    const float lvs = lg2f_(fabsf(vs[0]));
    const int tx = threadIdx.x, ty = threadIdx.y;

    #pragma unroll
    for (int i = 0; i < 4; i++) {
        int bl = ty + 8 * i;
        size_t base = ((size_t)(b0 + bl) * TT + (t0 + tx)) * 3;
        float v  = x[base];
        float Fc = x[base + 1];
        float Fs = x[base + 2];
        float av = fabsf(v);
        float p  = ex2f_(a0 * (lg2f_(av) - lvs));   // |v/vs|^alpha
        float w  = ex2f_(-LOG2E * p);               // exp(-p)
        float g  = fmaf(Fs - Fc, w, Fc);
        float sg = (v > 0.f) ? 1.f : ((v < 0.f) ? -1.f : 0.f);
        float k  = g * sg;
        float c2 = __fdividef(av, g) * C2COEF;      // dt*ln2*|v|/g
        tile[bl][tx] = make_float4(v, k, c2, Fs);
    }
    __syncthreads();
    #pragma unroll
    for (int i = 0; i < 4; i++) {
        int tl = ty + 8 * i;
        g_pre[(size_t)(t0 + tl) * BB + (b0 + tx)] = tile[tx][tl];
    }
}

// ---------------- Kernel 2: sequential scan ----------------
// Off-path MLP block: from (vnext, pred) produce Lgh = lg2(1+2^(y*log2e))
// and qs = d(Lg)/d(sz) = (Sum w2*w1*sech^2)*log2e * sigmoid(y).
__device__ __forceinline__ void mlp_off(
    float vnext, float pred,
    const float* w0, const float* w1r, const float* bv,
    const float* w2s, const float* w21, float b2s,
    float& Lgh, float& qs)
{
    float ay = b2s, by = 0.f, aq = 0.f, bq = 0.f;
    #pragma unroll
    for (int q2 = 0; q2 < 8; q2++) {
        float z = fmaf(pred, w1r[q2], fmaf(vnext, w0[q2], bv[q2]));
        float h = tanhf_(z);
        float s = fmaf(-h, h, 1.0f);          // sech^2
        if (q2 & 1) { by = fmaf(h, w2s[q2], by); bq = fmaf(s, w21[q2], bq); }
        else        { ay = fmaf(h, w2s[q2], ay); aq = fmaf(s, w21[q2], aq); }
    }
    float ys = ay + by;
    float qv = aq + bq;
    ys += __shfl_xor_sync(0xffffffffu, ys, 1);
    qv += __shfl_xor_sync(0xffffffffu, qv, 1);
    ys += __shfl_xor_sync(0xffffffffu, ys, 2);
    qv += __shfl_xor_sync(0xffffffffu, qv, 2);
    ys += __shfl_xor_sync(0xffffffffu, ys, 4);
    qv += __shfl_xor_sync(0xffffffffu, qv, 4);   // ys = y*log2e (full sum)
    float e   = ex2f_(ys);
    float Lgn = lg2f_(1.0f + e);                 // sp(y)*log2e
    float sig = ex2f_(ys - Lgn);                 // sigmoid(y) = e/(1+e)
    Lgh = Lgn;
    qs  = qv * sig;
}

__device__ __forceinline__ float lugre_step(
    float4 pk, float vnext, float& sz, float& szp, float& Lgh, float& qs,
    const float* w0, const float* w1r, const float* bv,
    const float* w2s, const float* w21,
    float b2s, float s1, float s2)
{
    float v = pk.x, k = pk.y, c2 = pk.z, Fs = pk.w;
    float invg = c2 * INVC;                  // |v|/g
    // ---- critical path: correction + state update ----
    float dsz = sz - szp;                    // sz_t - predictor
    float Lg  = fmaf(dsz, qs, Lgh);          // corrected sp(y_t)*log2e
    float u   = c2 * Lg;                     // dt*sigma0*|v|/g
    float rr  = fmaf(u, 0.16666667f, -0.5f);
    float qq  = fmaf(u, rr, 1.0f);
    float m   = u * qq;                      // 1 - exp(-u)
    float d   = sz - k;
    float szn = fmaf(-d, m, sz);             // pre-clip sz_{t+1}
    float zd  = fmaf(-szn, invg, v);
    float szc = fminf(fmaxf(szn, -Fs), Fs);
    float F   = fmaf(s1, zd, fmaf(s2, v, szc));
    // ---- off-path: MLP for step t+1 with predictor sz_t ----
    float pred = sz;
    szp = sz;
    sz  = szc;
    mlp_off(vnext, pred, w0, w1r, bv, w2s, w21, b2s, Lgh, qs);
    return F;
}

__global__ void __launch_bounds__(128) lugre_scan(
    const float* __restrict__ W1, const float* __restrict__ b1,
    const float* __restrict__ W2, const float* __restrict__ b2,
    const float* __restrict__ sg1, const float* __restrict__ sg2,
    float* __restrict__ out)
{
    const int lane = threadIdx.x & 31;
    const int warp = (blockIdx.x * blockDim.x + threadIdx.x) >> 5;  // 0..1023
    const int slot = lane >> 3;     // 0..3 : batch slot in warp
    const int r    = lane & 7;      // 0..7 : lane within batch group
    const int b    = warp * 4 + slot;

    float w0[8], w1r[8], bv[8], w2s[8], w21[8];
    #pragma unroll
    for (int q = 0; q < 8; q++) {
        int j = r * 8 + q;
        w0[q]  = W1[j];               // W1[0][j]
        w1r[q] = W1[HH + j];          // W1[1][j]
        bv[q]  = b1[j];
        w2s[q] = W2[j] * LOG2E;       // fold log2e into W2
        w21[q] = w2s[q] * w1r[q];     // for the derivative q-term
    }
    const float b2s = b2[0] * LOG2E * 0.125f;   // b2 split over 8 lanes
    const float s1 = fabsf(sg1[0]);
    const float s2 = fabsf(sg2[0]);

    const float4* p = g_pre + b;
    float* outp = out + (size_t)b * TT;

    float4 c0 = __ldg(p), c1 = __ldg(p + BB), c2v = __ldg(p + 2 * BB), c3 = __ldg(p + 3 * BB);
    float4 n0 = c0, n1 = c1, n2 = c2v, n3 = c3;

    float sz = 0.0f, szp = 0.0f;   // predictor = 0 = sz_0 (exact at t=0)
    float Lgh, qs;
    mlp_off(c0.x, 0.0f, w0, w1r, bv, w2s, w21, b2s, Lgh, qs);

    for (int tb = 0; tb < TT; tb += 4) {
        if (tb + 4 < TT) {
            const float4* pn = p + (size_t)(tb + 4) * BB;
            n0 = __ldg(pn); n1 = __ldg(pn + BB); n2 = __ldg(pn + 2 * BB); n3 = __ldg(pn + 3 * BB);
        }
        float f0 = lugre_step(c0,  c1.x, sz, szp, Lgh, qs, w0, w1r, bv, w2s, w21, b2s, s1, s2);
        float f1 = lugre_step(c1,  c2v.x, sz, szp, Lgh, qs, w0, w1r, bv, w2s, w21, b2s, s1, s2);
        float f2 = lugre_step(c2v, c3.x, sz, szp, Lgh, qs, w0, w1r, bv, w2s, w21, b2s, s1, s2);
        float f3 = lugre_step(c3,  n0.x, sz, szp, Lgh, qs, w0, w1r, bv, w2s, w21, b2s, s1, s2);
        if (r == 0) {
            *reinterpret_cast<float4*>(outp + tb) = make_float4(f0, f1, f2, f3);
        }
        c0 = n0; c1 = n1; c2v = n2; c3 = n3;
    }
}

// ---------------- launch ----------------
extern "C" void kernel_launch(void* const* d_in, const int* in_sizes, int n_in,
                              void* d_out, int out_size) {
    const float* x     = (const float*)d_in[0];
    const float* sig1  = (const float*)d_in[1];
    const float* sig2  = (const float*)d_in[2];
    const float* alpha = (const float*)d_in[3];
    const float* vs    = (const float*)d_in[4];
    const float* W1    = (const float*)d_in[5];
    const float* b1    = (const float*)d_in[6];
    const float* W2    = (const float*)d_in[7];
    const float* b2    = (const float*)d_in[8];
    float* out = (float*)d_out;

    dim3 blk(32, 8);
    dim3 grd(TT / 32, BB / 32);
    lugre_pre<<<grd, blk>>>(x, alpha, vs);

    lugre_scan<<<256, 128>>>(W1, b1, W2, b2, sig1, sig2, out);
}

// round 4
// speedup vs baseline: 1.2314x; 1.2314x over previous
#include <cuda_runtime.h>
#include <cuda_bf16.h>
#include <cstdint>

// LuGreCell: B=4096, T=2048, S=1, H=64.
// Kernel 1: precompute per (b,t): v, k=g*sign(v), c2=dt*ln2*|v|/g, Fs;
//           transpose to time-major [T][B] float4.
// Kernel 2: sequential scan, 1024 warps (4 batches/warp, 8 lanes/batch).
//   DEPTH-2 SOFTWARE PIPELINE: the MLP for step i+2 is evaluated at
//   pred = S_i (two iterations of slack); on the critical sz->sz chain only
//   a first-order correction + state update remain (~8 FMA-class ops).

#define BB 4096
#define TT 2048
#define HH 64

__device__ float4 g_pre[(size_t)BB * TT];  // 134 MB static scratch

__device__ __forceinline__ float ex2f_(float x){ float y; asm("ex2.approx.f32 %0, %1;":"=f"(y):"f"(x)); return y; }
__device__ __forceinline__ float lg2f_(float x){ float y; asm("lg2.approx.f32 %0, %1;":"=f"(y):"f"(x)); return y; }
__device__ __forceinline__ float tanhf_(float x){ float y; asm("tanh.approx.f32 %0, %1;":"=f"(y):"f"(x)); return y; }

#define LOG2E 1.4426950408889634f
#define C2COEF 6.931471805599453e-4f        /* dt*ln2 */
#define INVC   1442.6950408889634f          /* 1/(dt*ln2) */

// ---------------- Kernel 1: precompute + transpose ----------------
__global__ void __launch_bounds__(256) lugre_pre(
    const float* __restrict__ x,        // [B, T, 3]: v, F_c, F_s
    const float* __restrict__ alpha,
    const float* __restrict__ vs)
{
    __shared__ float4 tile[32][33];
    const int t0 = blockIdx.x * 32;
    const int b0 = blockIdx.y * 32;
    const float a0  = alpha[0];
    const float lvs = lg2f_(fabsf(vs[0]));
    const int tx = threadIdx.x, ty = threadIdx.y;

    #pragma unroll
    for (int i = 0; i < 4; i++) {
        int bl = ty + 8 * i;
        size_t base = ((size_t)(b0 + bl) * TT + (t0 + tx)) * 3;
        float v  = x[base];
        float Fc = x[base + 1];
        float Fs = x[base + 2];
        float av = fabsf(v);
        float p  = ex2f_(a0 * (lg2f_(av) - lvs));   // |v/vs|^alpha
        float w  = ex2f_(-LOG2E * p);               // exp(-p)
        float g  = fmaf(Fs - Fc, w, Fc);
        float sg = (v > 0.f) ? 1.f : ((v < 0.f) ? -1.f : 0.f);
        float k  = g * sg;
        float c2 = __fdividef(av, g) * C2COEF;      // dt*ln2*|v|/g
        tile[bl][tx] = make_float4(v, k, c2, Fs);
    }
    __syncthreads();
    #pragma unroll
    for (int i = 0; i < 4; i++) {
        int tl = ty + 8 * i;
        g_pre[(size_t)(t0 + tl) * BB + (b0 + tx)] = tile[tx][tl];
    }
}

// ---------------- Kernel 2: sequential scan ----------------
// MLP block evaluated at (vstep, pred): Lgh = lg2(1+2^(y*log2e)) = sp(y)*log2e,
// qs = d(Lgh)/d(sz) = (sum w2*w1*sech^2)*log2e*sigmoid(y).
__device__ __forceinline__ void mlp_off(
    float vstep, float pred,
    const float* w0, const float* w1r, const float* bv,
    const float* w2s, const float* w21, float b2s,
    float& Lgh, float& qs)
{
    float ay = b2s, by = 0.f, aq = 0.f, bq = 0.f;
    #pragma unroll
    for (int q2 = 0; q2 < 8; q2++) {
        float z = fmaf(pred, w1r[q2], fmaf(vstep, w0[q2], bv[q2]));
        float h = tanhf_(z);
        float s = fmaf(-h, h, 1.0f);          // sech^2
        if (q2 & 1) { by = fmaf(h, w2s[q2], by); bq = fmaf(s, w21[q2], bq); }
        else        { ay = fmaf(h, w2s[q2], ay); aq = fmaf(s, w21[q2], aq); }
    }
    float ys = ay + by;
    float qv = aq + bq;
    ys += __shfl_xor_sync(0xffffffffu, ys, 1);
    qv += __shfl_xor_sync(0xffffffffu, qv, 1);
    ys += __shfl_xor_sync(0xffffffffu, ys, 2);
    qv += __shfl_xor_sync(0xffffffffu, qv, 2);
    ys += __shfl_xor_sync(0xffffffffu, ys, 4);
    qv += __shfl_xor_sync(0xffffffffu, qv, 4);   // ys = y*log2e (full sum)
    float e   = ex2f_(ys);
    float Lgn = lg2f_(1.0f + e);                 // sp(y)*log2e
    float sig = ex2f_(ys - Lgn);                 // sigmoid(y)
    Lgh = Lgn;
    qs  = qv * sig;
}

// One scan step (step i). Consumes this parity's (Lgh,qs,pr) computed at
// pred = S_{i-2}; refills the same parity with the MLP for step i+2 at
// pred = S_i. Critical chain: dsz->Lg->u->Taylor->szn->clamp only.
__device__ __forceinline__ float lugre_step(
    float4 pk, float vn2, float& S,
    float& Lgh, float& qs, float& pr,
    const float* w0, const float* w1r, const float* bv,
    const float* w2s, const float* w21,
    float b2s, float s1, float s2)
{
    float v = pk.x, k = pk.y, c2 = pk.z, Fs = pk.w;
    float pred = S;   // input state of this step; predictor for step i+2
    // ---- issue off-path MLP for step i+2 (independent of chain below) ----
    float LghN, qsN;
    mlp_off(vn2, pred, w0, w1r, bv, w2s, w21, b2s, LghN, qsN);
    // ---- critical chain ----
    float dsz = S - pr;                      // S_i - S_{i-2}
    float Lg  = fmaf(dsz, qs, Lgh);          // corrected sp(y_i)*log2e
    float u   = c2 * Lg;                     // dt*sigma0*|v|/g
    float rr  = fmaf(u, 0.16666667f, -0.5f);
    float qq  = fmaf(u, rr, 1.0f);
    float m   = u * qq;                      // 1 - exp(-u)
    float d   = S - k;
    float szn = fmaf(-d, m, S);              // pre-clip sz_{i+1}
    float invg = c2 * INVC;                  // |v|/g
    float zd  = fmaf(-szn, invg, v);
    float szc = fminf(fmaxf(szn, -Fs), Fs);
    float F   = fmaf(s1, zd, fmaf(s2, v, szc));
    // ---- rotate pipeline state ----
    Lgh = LghN; qs = qsN; pr = pred;
    S = szc;
    return F;
}

__global__ void __launch_bounds__(128) lugre_scan(
    const float* __restrict__ W1, const float* __restrict__ b1,
    const float* __restrict__ W2, const float* __restrict__ b2,
    const float* __restrict__ sg1, const float* __restrict__ sg2,
    float* __restrict__ out)
{
    const int lane = threadIdx.x & 31;
    const int warp = (blockIdx.x * blockDim.x + threadIdx.x) >> 5;  // 0..1023
    const int slot = lane >> 3;     // 0..3 : batch slot in warp
    const int r    = lane & 7;      // 0..7 : lane within batch group
    const int b    = warp * 4 + slot;

    float w0[8], w1r[8], bv[8], w2s[8], w21[8];
    #pragma unroll
    for (int q = 0; q < 8; q++) {
        int j = r * 8 + q;
        w0[q]  = W1[j];               // W1[0][j]
        w1r[q] = W1[HH + j];          // W1[1][j]
        bv[q]  = b1[j];
        w2s[q] = W2[j] * LOG2E;       // fold log2e into W2
        w21[q] = w2s[q] * w1r[q];     // derivative weights
    }
    const float b2s = b2[0] * LOG2E * 0.125f;   // b2 split over 8 lanes
    const float s1 = fabsf(sg1[0]);
    const float s2 = fabsf(sg2[0]);

    const float4* p = g_pre + b;
    float* outp = out + (size_t)b * TT;

    float4 c0 = __ldg(p), c1 = __ldg(p + BB), c2v = __ldg(p + 2 * BB), c3 = __ldg(p + 3 * BB);
    float4 n0 = c0, n1 = c1, n2 = c2v, n3 = c3;

    float S = 0.0f;
    // Prologue: MLP for step 0 and step 1, both at pred = S_0 = 0 (step 0 exact).
    float Lgh0, qs0, Lgh1, qs1;
    float pr0 = 0.0f, pr1 = 0.0f;
    mlp_off(c0.x, 0.0f, w0, w1r, bv, w2s, w21, b2s, Lgh0, qs0);
    mlp_off(c1.x, 0.0f, w0, w1r, bv, w2s, w21, b2s, Lgh1, qs1);

    for (int tb = 0; tb < TT; tb += 4) {
        if (tb + 4 < TT) {
            const float4* pn = p + (size_t)(tb + 4) * BB;
            n0 = __ldg(pn); n1 = __ldg(pn + BB); n2 = __ldg(pn + 2 * BB); n3 = __ldg(pn + 3 * BB);
        }
        float f0 = lugre_step(c0,  c2v.x, S, Lgh0, qs0, pr0, w0, w1r, bv, w2s, w21, b2s, s1, s2);
        float f1 = lugre_step(c1,  c3.x,  S, Lgh1, qs1, pr1, w0, w1r, bv, w2s, w21, b2s, s1, s2);
        float f2 = lugre_step(c2v, n0.x,  S, Lgh0, qs0, pr0, w0, w1r, bv, w2s, w21, b2s, s1, s2);
        float f3 = lugre_step(c3,  n1.x,  S, Lgh1, qs1, pr1, w0, w1r, bv, w2s, w21, b2s, s1, s2);
        if (r == 0) {
            *reinterpret_cast<float4*>(outp + tb) = make_float4(f0, f1, f2, f3);
        }
        c0 = n0; c1 = n1; c2v = n2; c3 = n3;
    }
}

// ---------------- launch ----------------
extern "C" void kernel_launch(void* const* d_in, const int* in_sizes, int n_in,
                              void* d_out, int out_size) {
    const float* x     = (const float*)d_in[0];
    const float* sig1  = (const float*)d_in[1];
    const float* sig2  = (const float*)d_in[2];
    const float* alpha = (const float*)d_in[3];
    const float* vs    = (const float*)d_in[4];
    const float* W1    = (const float*)d_in[5];
    const float* b1    = (const float*)d_in[6];
    const float* W2    = (const float*)d_in[7];
    const float* b2    = (const float*)d_in[8];
    float* out = (float*)d_out;

    dim3 blk(32, 8);
    dim3 grd(TT / 32, BB / 32);
    lugre_pre<<<grd, blk>>>(x, alpha, vs);

    lugre_scan<<<256, 128>>>(W1, b1, W2, b2, sig1, sig2, out);
}

// round 5
// speedup vs baseline: 1.3530x; 1.0988x over previous
#include <cuda_runtime.h>
#include <cuda_bf16.h>
#include <cstdint>

// LuGreCell: B=4096, T=2048, S=1, H=64.
// Kernel 1: precompute per (b,t): v, k=g*sign(v), c2=dt*ln2*|v|/g, Fs;
//           transpose to time-major [T][B] float4.
// Kernel 2: sequential scan, 1024 warps (4 batches/warp, 8 lanes/batch).
//   DEPTH-4 SOFTWARE PIPELINE: MLP for step i+4 evaluated at pred=S_i
//   (4 steps of slack hides the ~190cyc MLP latency incl. shfl chain);
//   on-path: first-order correction + state update (~8 FMA-class ops).
//   Distance-8 input prefetch (2 blocks in flight) hides DRAM latency.

#define BB 4096
#define TT 2048
#define HH 64

__device__ float4 g_pre[(size_t)BB * TT];  // 134 MB static scratch

__device__ __forceinline__ float ex2f_(float x){ float y; asm("ex2.approx.f32 %0, %1;":"=f"(y):"f"(x)); return y; }
__device__ __forceinline__ float lg2f_(float x){ float y; asm("lg2.approx.f32 %0, %1;":"=f"(y):"f"(x)); return y; }
__device__ __forceinline__ float tanhf_(float x){ float y; asm("tanh.approx.f32 %0, %1;":"=f"(y):"f"(x)); return y; }

#define LOG2E 1.4426950408889634f
#define C2COEF 6.931471805599453e-4f        /* dt*ln2 */
#define INVC   1442.6950408889634f          /* 1/(dt*ln2) */

// ---------------- Kernel 1: precompute + transpose ----------------
__global__ void __launch_bounds__(256) lugre_pre(
    const float* __restrict__ x,        // [B, T, 3]: v, F_c, F_s
    const float* __restrict__ alpha,
    const float* __restrict__ vs)
{
    __shared__ float4 tile[32][33];
    const int t0 = blockIdx.x * 32;
    const int b0 = blockIdx.y * 32;
    const float a0  = alpha[0];
    const float lvs = lg2f_(fabsf(vs[0]));
    const int tx = threadIdx.x, ty = threadIdx.y;

    #pragma unroll
    for (int i = 0; i < 4; i++) {
        int bl = ty + 8 * i;
        size_t base = ((size_t)(b0 + bl) * TT + (t0 + tx)) * 3;
        float v  = x[base];
        float Fc = x[base + 1];
        float Fs = x[base + 2];
        float av = fabsf(v);
        float p  = ex2f_(a0 * (lg2f_(av) - lvs));   // |v/vs|^alpha
        float w  = ex2f_(-LOG2E * p);               // exp(-p)
        float g  = fmaf(Fs - Fc, w, Fc);
        float sg = (v > 0.f) ? 1.f : ((v < 0.f) ? -1.f : 0.f);
        float k  = g * sg;
        float c2 = __fdividef(av, g) * C2COEF;      // dt*ln2*|v|/g
        tile[bl][tx] = make_float4(v, k, c2, Fs);
    }
    __syncthreads();
    #pragma unroll
    for (int i = 0; i < 4; i++) {
        int tl = ty + 8 * i;
        g_pre[(size_t)(t0 + tl) * BB + (b0 + tx)] = tile[tx][tl];
    }
}

// ---------------- Kernel 2: sequential scan ----------------
// MLP at (vstep, pred): Lgh = sp(y)*log2e, qs = d(Lgh)/d(sz).
__device__ __forceinline__ void mlp_off(
    float vstep, float pred,
    const float* w0, const float* w1r, const float* bv,
    const float* w2s, const float* w21, float b2s,
    float& Lgh, float& qs)
{
    float ay = b2s, by = 0.f, aq = 0.f, bq = 0.f;
    #pragma unroll
    for (int q2 = 0; q2 < 8; q2++) {
        float z = fmaf(pred, w1r[q2], fmaf(vstep, w0[q2], bv[q2]));
        float h = tanhf_(z);
        float s = fmaf(-h, h, 1.0f);          // sech^2
        if (q2 & 1) { by = fmaf(h, w2s[q2], by); bq = fmaf(s, w21[q2], bq); }
        else        { ay = fmaf(h, w2s[q2], ay); aq = fmaf(s, w21[q2], aq); }
    }
    float ys = ay + by;
    float qv = aq + bq;
    ys += __shfl_xor_sync(0xffffffffu, ys, 1);
    qv += __shfl_xor_sync(0xffffffffu, qv, 1);
    ys += __shfl_xor_sync(0xffffffffu, ys, 2);
    qv += __shfl_xor_sync(0xffffffffu, qv, 2);
    ys += __shfl_xor_sync(0xffffffffu, ys, 4);
    qv += __shfl_xor_sync(0xffffffffu, qv, 4);   // ys = y*log2e (full sum)
    float e   = ex2f_(ys);
    float Lgn = lg2f_(1.0f + e);                 // sp(y)*log2e
    float sig = ex2f_(ys - Lgn);                 // sigmoid(y)
    Lgh = Lgn;
    qs  = qv * sig;
}

// Step i: consumes slot (Lgh,qs,pr) built at pred=S_{i-4}; refills the
// slot for step i+4 at pred=S_i. Critical chain: correction + update only.
__device__ __forceinline__ float lugre_step(
    float4 pk, float vn4, float& S,
    float& Lgh, float& qs, float& pr,
    const float* w0, const float* w1r, const float* bv,
    const float* w2s, const float* w21,
    float b2s, float s1, float s2)
{
    float v = pk.x, k = pk.y, c2 = pk.z, Fs = pk.w;
    float pred = S;   // state entering step i = predictor for step i+4
    // ---- off-path: MLP for step i+4 (4 steps of slack) ----
    float LghN, qsN;
    mlp_off(vn4, pred, w0, w1r, bv, w2s, w21, b2s, LghN, qsN);
    // ---- critical chain ----
    float dsz = S - pr;                      // S_i - S_{i-4}
    float Lg  = fmaf(dsz, qs, Lgh);          // corrected sp(y_i)*log2e
    float u   = c2 * Lg;                     // dt*sigma0*|v|/g
    float rr  = fmaf(u, 0.16666667f, -0.5f);
    float qq  = fmaf(u, rr, 1.0f);
    float m   = u * qq;                      // 1 - exp(-u)
    float d   = S - k;
    float szn = fmaf(-d, m, S);              // pre-clip sz_{i+1}
    float invg = c2 * INVC;                  // |v|/g
    float zd  = fmaf(-szn, invg, v);
    float szc = fminf(fmaxf(szn, -Fs), Fs);
    float F   = fmaf(s1, zd, fmaf(s2, v, szc));
    // ---- rotate slot ----
    Lgh = LghN; qs = qsN; pr = pred;
    S = szc;
    return F;
}

__global__ void __launch_bounds__(128) lugre_scan(
    const float* __restrict__ W1, const float* __restrict__ b1,
    const float* __restrict__ W2, const float* __restrict__ b2,
    const float* __restrict__ sg1, const float* __restrict__ sg2,
    float* __restrict__ out)
{
    const int lane = threadIdx.x & 31;
    const int warp = (blockIdx.x * blockDim.x + threadIdx.x) >> 5;  // 0..1023
    const int slot = lane >> 3;     // 0..3 : batch slot in warp
    const int r    = lane & 7;      // 0..7 : lane within batch group
    const int b    = warp * 4 + slot;

    float w0[8], w1r[8], bv[8], w2s[8], w21[8];
    #pragma unroll
    for (int q = 0; q < 8; q++) {
        int j = r * 8 + q;
        w0[q]  = W1[j];               // W1[0][j]
        w1r[q] = W1[HH + j];          // W1[1][j]
        bv[q]  = b1[j];
        w2s[q] = W2[j] * LOG2E;       // fold log2e into W2
        w21[q] = w2s[q] * w1r[q];     // derivative weights
    }
    const float b2s = b2[0] * LOG2E * 0.125f;   // b2 split over 8 lanes
    const float s1 = fabsf(sg1[0]);
    const float s2 = fabsf(sg2[0]);

    const float4* p = g_pre + b;
    float* outp = out + (size_t)b * TT;

    // Two prefetch stages: c = block t, m = block t+4, n = block t+8.
    float4 c0 = __ldg(p),          c1 = __ldg(p + BB),
           c2v = __ldg(p + 2*BB),  c3 = __ldg(p + 3*BB);
    const float4* pm = p + (size_t)4 * BB;
    float4 m0 = __ldg(pm),         m1 = __ldg(pm + BB),
           m2 = __ldg(pm + 2*BB),  m3 = __ldg(pm + 3*BB);

    float S = 0.0f;
    // Prologue: slots for steps 0..3, all at pred = S_0 = 0 (step 0 exact,
    // steps 1-3 first-order corrected from pred 0).
    float L0, q0, L1, q1, L2, q2, L3, q3;
    float pr0 = 0.f, pr1 = 0.f, pr2 = 0.f, pr3 = 0.f;
    mlp_off(c0.x, 0.f, w0, w1r, bv, w2s, w21, b2s, L0, q0);
    mlp_off(c1.x, 0.f, w0, w1r, bv, w2s, w21, b2s, L1, q1);
    mlp_off(c2v.x, 0.f, w0, w1r, bv, w2s, w21, b2s, L2, q2);
    mlp_off(c3.x, 0.f, w0, w1r, bv, w2s, w21, b2s, L3, q3);

    for (int tb = 0; tb < TT; tb += 4) {
        // prefetch block tb+8 (clamped; stale values only feed refills
        // whose slots are never consumed after the loop ends)
        int tn = tb + 8 <= TT - 4 ? tb + 8 : TT - 4;
        const float4* pn = p + (size_t)tn * BB;
        float4 n0 = __ldg(pn),        n1 = __ldg(pn + BB),
               n2 = __ldg(pn + 2*BB), n3 = __ldg(pn + 3*BB);

        float f0 = lugre_step(c0,  m0.x, S, L0, q0, pr0, w0, w1r, bv, w2s, w21, b2s, s1, s2);
        float f1 = lugre_step(c1,  m1.x, S, L1, q1, pr1, w0, w1r, bv, w2s, w21, b2s, s1, s2);
        float f2 = lugre_step(c2v, m2.x, S, L2, q2, pr2, w0, w1r, bv, w2s, w21, b2s, s1, s2);
        float f3 = lugre_step(c3,  m3.x, S, L3, q3, pr3, w0, w1r, bv, w2s, w21, b2s, s1, s2);
        if (r == 0) {
            *reinterpret_cast<float4*>(outp + tb) = make_float4(f0, f1, f2, f3);
        }
        c0 = m0; c1 = m1; c2v = m2; c3 = m3;
        m0 = n0; m1 = n1; m2 = n2; m3 = n3;
    }
}

// ---------------- launch ----------------
extern "C" void kernel_launch(void* const* d_in, const int* in_sizes, int n_in,
                              void* d_out, int out_size) {
    const float* x     = (const float*)d_in[0];
    const float* sig1  = (const float*)d_in[1];
    const float* sig2  = (const float*)d_in[2];
    const float* alpha = (const float*)d_in[3];
    const float* vs    = (const float*)d_in[4];
    const float* W1    = (const float*)d_in[5];
    const float* b1    = (const float*)d_in[6];
    const float* W2    = (const float*)d_in[7];
    const float* b2    = (const float*)d_in[8];
    float* out = (float*)d_out;

    dim3 blk(32, 8);
    dim3 grd(TT / 32, BB / 32);
    lugre_pre<<<grd, blk>>>(x, alpha, vs);

    lugre_scan<<<256, 128>>>(W1, b1, W2, b2, sig1, sig2, out);
}

// round 6
// speedup vs baseline: 1.4298x; 1.0568x over previous
#include <cuda_runtime.h>
#include <cuda_bf16.h>
#include <cstdint>

// LuGreCell: B=4096, T=2048, S=1, H=64.
// Kernel 1: precompute per (b,t): v, k=g*sign(v), c2=dt*ln2*|v|/g, Fs;
//           transpose to time-major [T][B] float4. (HBM-bound, ~42us)
// Kernel 2: sequential scan, 1024 warps (4 batches/warp, 8 lanes/batch),
//   launched 128 blocks x 256 thr -> uniform 2 warps/SMSP on 128 SMs.
//   DEPTH-4 SOFTWARE PIPELINE: MLP for step i+4 evaluated at pred=S_i;
//   on-path only a first-order correction + state update.
//   Derivative qs amortized: full MLP (with d/dsz) once per 4 steps,
//   lite MLP (value only) otherwise — qs enters only at 2nd order.

#define BB 4096
#define TT 2048
#define HH 64

__device__ float4 g_pre[(size_t)BB * TT];  // 134 MB static scratch

__device__ __forceinline__ float ex2f_(float x){ float y; asm("ex2.approx.f32 %0, %1;":"=f"(y):"f"(x)); return y; }
__device__ __forceinline__ float lg2f_(float x){ float y; asm("lg2.approx.f32 %0, %1;":"=f"(y):"f"(x)); return y; }
__device__ __forceinline__ float tanhf_(float x){ float y; asm("tanh.approx.f32 %0, %1;":"=f"(y):"f"(x)); return y; }

#define LOG2E 1.4426950408889634f
#define C2COEF 6.931471805599453e-4f        /* dt*ln2 */
#define INVC   1442.6950408889634f          /* 1/(dt*ln2) */

// ---------------- Kernel 1: precompute + transpose ----------------
__global__ void __launch_bounds__(256) lugre_pre(
    const float* __restrict__ x,        // [B, T, 3]: v, F_c, F_s
    const float* __restrict__ alpha,
    const float* __restrict__ vs)
{
    __shared__ float4 tile[32][33];
    const int t0 = blockIdx.x * 32;
    const int b0 = blockIdx.y * 32;
    const float a0  = alpha[0];
    const float lvs = lg2f_(fabsf(vs[0]));
    const int tx = threadIdx.x, ty = threadIdx.y;

    #pragma unroll
    for (int i = 0; i < 4; i++) {
        int bl = ty + 8 * i;
        size_t base = ((size_t)(b0 + bl) * TT + (t0 + tx)) * 3;
        float v  = x[base];
        float Fc = x[base + 1];
        float Fs = x[base + 2];
        float av = fabsf(v);
        float p  = ex2f_(a0 * (lg2f_(av) - lvs));   // |v/vs|^alpha
        float w  = ex2f_(-LOG2E * p);               // exp(-p)
        float g  = fmaf(Fs - Fc, w, Fc);
        float sg = (v > 0.f) ? 1.f : ((v < 0.f) ? -1.f : 0.f);
        float k  = g * sg;
        float c2 = __fdividef(av, g) * C2COEF;      // dt*ln2*|v|/g
        tile[bl][tx] = make_float4(v, k, c2, Fs);
    }
    __syncthreads();
    #pragma unroll
    for (int i = 0; i < 4; i++) {
        int tl = ty + 8 * i;
        g_pre[(size_t)(t0 + tl) * BB + (b0 + tx)] = tile[tx][tl];
    }
}

// ---------------- Kernel 2: sequential scan ----------------
// FULL refill: Lgh = sp(y)*log2e AND qs = d(Lgh)/d(sz).
__device__ __forceinline__ void mlp_full(
    float vstep, float pred,
    const float* w0, const float* w1r, const float* bv,
    const float* w2s, const float* w21, float b2s,
    float& Lgh, float& qs)
{
    float ay = b2s, by = 0.f, aq = 0.f, bq = 0.f;
    #pragma unroll
    for (int q2 = 0; q2 < 8; q2++) {
        float z = fmaf(pred, w1r[q2], fmaf(vstep, w0[q2], bv[q2]));
        float h = tanhf_(z);
        float s = fmaf(-h, h, 1.0f);          // sech^2
        if (q2 & 1) { by = fmaf(h, w2s[q2], by); bq = fmaf(s, w21[q2], bq); }
        else        { ay = fmaf(h, w2s[q2], ay); aq = fmaf(s, w21[q2], aq); }
    }
    float ys = ay + by;
    float qv = aq + bq;
    ys += __shfl_xor_sync(0xffffffffu, ys, 1);
    qv += __shfl_xor_sync(0xffffffffu, qv, 1);
    ys += __shfl_xor_sync(0xffffffffu, ys, 2);
    qv += __shfl_xor_sync(0xffffffffu, qv, 2);
    ys += __shfl_xor_sync(0xffffffffu, ys, 4);
    qv += __shfl_xor_sync(0xffffffffu, qv, 4);   // ys = y*log2e
    float e   = ex2f_(ys);
    float Lgn = lg2f_(1.0f + e);                 // sp(y)*log2e
    float sig = ex2f_(ys - Lgn);                 // sigmoid(y)
    Lgh = Lgn;
    qs  = qv * sig;
}

// LITE refill: Lgh only (no derivative).
__device__ __forceinline__ void mlp_lite(
    float vstep, float pred,
    const float* w0, const float* w1r, const float* bv,
    const float* w2s, float b2s,
    float& Lgh)
{
    float ay = b2s, by = 0.f;
    #pragma unroll
    for (int q2 = 0; q2 < 8; q2++) {
        float z = fmaf(pred, w1r[q2], fmaf(vstep, w0[q2], bv[q2]));
        float h = tanhf_(z);
        if (q2 & 1) by = fmaf(h, w2s[q2], by);
        else        ay = fmaf(h, w2s[q2], ay);
    }
    float ys = ay + by;
    ys += __shfl_xor_sync(0xffffffffu, ys, 1);
    ys += __shfl_xor_sync(0xffffffffu, ys, 2);
    ys += __shfl_xor_sync(0xffffffffu, ys, 4);
    float e = ex2f_(ys);
    Lgh = lg2f_(1.0f + e);
}

// Step i: consumes slot (Lgh,pr) built at pred=S_{i-4} plus shared qs;
// refills slot for step i+4 at pred=S_i. FULL derivative only when FULL.
template<bool FULL>
__device__ __forceinline__ float lugre_step(
    float4 pk, float vn4, float& S,
    float& Lgh, float& pr, float& qs,
    const float* w0, const float* w1r, const float* bv,
    const float* w2s, const float* w21,
    float b2s, float s1, float s2)
{
    float v = pk.x, k = pk.y, c2 = pk.z, Fs = pk.w;
    float pred = S;   // state entering step i = predictor for step i+4
    // ---- off-path refill for step i+4 ----
    float LghN;
    float qsN = qs;
    if (FULL) mlp_full(vn4, pred, w0, w1r, bv, w2s, w21, b2s, LghN, qsN);
    else      mlp_lite(vn4, pred, w0, w1r, bv, w2s, b2s, LghN);
    // ---- critical chain ----
    float dsz = S - pr;                      // S_i - S_{i-4}
    float Lg  = fmaf(dsz, qs, Lgh);          // corrected sp(y_i)*log2e
    float u   = c2 * Lg;                     // dt*sigma0*|v|/g
    float rr  = fmaf(u, 0.16666667f, -0.5f);
    float qq  = fmaf(u, rr, 1.0f);
    float m   = u * qq;                      // 1 - exp(-u)
    float d   = S - k;
    float szn = fmaf(-d, m, S);              // pre-clip sz_{i+1}
    float invg = c2 * INVC;                  // |v|/g
    float zd  = fmaf(-szn, invg, v);
    float szc = fminf(fmaxf(szn, -Fs), Fs);
    float F   = fmaf(s1, zd, fmaf(s2, v, szc));
    // ---- rotate ----
    Lgh = LghN; pr = pred;
    if (FULL) qs = qsN;
    S = szc;
    return F;
}

__global__ void __launch_bounds__(256) lugre_scan(
    const float* __restrict__ W1, const float* __restrict__ b1,
    const float* __restrict__ W2, const float* __restrict__ b2,
    const float* __restrict__ sg1, const float* __restrict__ sg2,
    float* __restrict__ out)
{
    const int lane = threadIdx.x & 31;
    const int warp = (blockIdx.x * blockDim.x + threadIdx.x) >> 5;  // 0..1023
    const int slot = lane >> 3;     // 0..3 : batch slot in warp
    const int r    = lane & 7;      // 0..7 : lane within batch group
    const int b    = warp * 4 + slot;

    float w0[8], w1r[8], bv[8], w2s[8], w21[8];
    #pragma unroll
    for (int q = 0; q < 8; q++) {
        int j = r * 8 + q;
        w0[q]  = W1[j];               // W1[0][j]
        w1r[q] = W1[HH + j];          // W1[1][j]
        bv[q]  = b1[j];
        w2s[q] = W2[j] * LOG2E;       // fold log2e into W2
        w21[q] = w2s[q] * w1r[q];     // derivative weights
    }
    const float b2s = b2[0] * LOG2E * 0.125f;   // b2 split over 8 lanes
    const float s1 = fabsf(sg1[0]);
    const float s2 = fabsf(sg2[0]);

    const float4* p = g_pre + b;
    float* outp = out + (size_t)b * TT;

    // Two prefetch stages: c = block t, m = block t+4, n = block t+8.
    float4 c0 = __ldg(p),          c1 = __ldg(p + BB),
           c2v = __ldg(p + 2*BB),  c3 = __ldg(p + 3*BB);
    const float4* pm = p + (size_t)4 * BB;
    float4 m0 = __ldg(pm),         m1 = __ldg(pm + BB),
           m2 = __ldg(pm + 2*BB),  m3 = __ldg(pm + 3*BB);

    float S = 0.0f;
    // Prologue: slots for steps 0..3, pred = S_0 = 0; full derivative once.
    float L0, L1, L2, L3, qs;
    float pr0 = 0.f, pr1 = 0.f, pr2 = 0.f, pr3 = 0.f;
    mlp_full(c0.x, 0.f, w0, w1r, bv, w2s, w21, b2s, L0, qs);
    mlp_lite(c1.x, 0.f, w0, w1r, bv, w2s, b2s, L1);
    mlp_lite(c2v.x, 0.f, w0, w1r, bv, w2s, b2s, L2);
    mlp_lite(c3.x, 0.f, w0, w1r, bv, w2s, b2s, L3);

    for (int tb = 0; tb < TT; tb += 4) {
        // prefetch block tb+8 (clamped; stale values only feed refills
        // whose slots are never consumed after the loop ends)
        int tn = tb + 8 <= TT - 4 ? tb + 8 : TT - 4;
        const float4* pn = p + (size_t)tn * BB;
        float4 n0 = __ldg(pn),        n1 = __ldg(pn + BB),
               n2 = __ldg(pn + 2*BB), n3 = __ldg(pn + 3*BB);

        float f0 = lugre_step<true >(c0,  m0.x, S, L0, pr0, qs, w0, w1r, bv, w2s, w21, b2s, s1, s2);
        float f1 = lugre_step<false>(c1,  m1.x, S, L1, pr1, qs, w0, w1r, bv, w2s, w21, b2s, s1, s2);
        float f2 = lugre_step<false>(c2v, m2.x, S, L2, pr2, qs, w0, w1r, bv, w2s, w21, b2s, s1, s2);
        float f3 = lugre_step<false>(c3,  m3.x, S, L3, pr3, qs, w0, w1r, bv, w2s, w21, b2s, s1, s2);
        if (r == 0) {
            *reinterpret_cast<float4*>(outp + tb) = make_float4(f0, f1, f2, f3);
        }
        c0 = m0; c1 = m1; c2v = m2; c3 = m3;
        m0 = n0; m1 = n1; m2 = n2; m3 = n3;
    }
}

// ---------------- launch ----------------
extern "C" void kernel_launch(void* const* d_in, const int* in_sizes, int n_in,
                              void* d_out, int out_size) {
    const float* x     = (const float*)d_in[0];
    const float* sig1  = (const float*)d_in[1];
    const float* sig2  = (const float*)d_in[2];
    const float* alpha = (const float*)d_in[3];
    const float* vs    = (const float*)d_in[4];
    const float* W1    = (const float*)d_in[5];
    const float* b1    = (const float*)d_in[6];
    const float* W2    = (const float*)d_in[7];
    const float* b2    = (const float*)d_in[8];
    float* out = (float*)d_out;

    dim3 blk(32, 8);
    dim3 grd(TT / 32, BB / 32);
    lugre_pre<<<grd, blk>>>(x, alpha, vs);

    // 128 blocks x 256 threads = 1024 warps, uniform 2 warps/SMSP on 128 SMs
    lugre_scan<<<128, 256>>>(W1, b1, W2, b2, sig1, sig2, out);
}